// round 2
// baseline (speedup 1.0000x reference)
#include <cuda_runtime.h>
#include <cuda_bf16.h>

// Problem constants (fixed by the dataset)
#define NN 100000
#define CC 48
#define EE 1600000
#define MM 20000
#define LL 10
#define LAMF 0.9f

#define SCAN_BLOCK 1024
#define SCAN_ITEMS 4
#define SCAN_TILE  (SCAN_BLOCK * SCAN_ITEMS)   // 4096
#define NTILES     ((NN + SCAN_TILE - 1) / SCAN_TILE)  // 25

// ---------------- device scratch (no allocations allowed) ----------------
__device__ int   d_deg[NN];        // in-degree (by col)
__device__ float d_dinv[NN];       // deg^-0.5
__device__ int   d_rowcnt[NN];     // out-count per row (CSR segment lengths)
__device__ int   d_rowptr[NN];     // CSR row offsets (exclusive scan of rowcnt)
__device__ int   d_cursor[NN];     // scatter cursors (init = rowptr)
__device__ int   d_winner[NN];     // last mask index targeting node (-1 = none)
__device__ int2  d_edges[EE];      // packed {col, weight-bits}, grouped by row
__device__ float d_G[NN * CC];     // G = Z with G[mask] = Y (last write wins)
__device__ float d_xA[NN * CC];    // ping
__device__ float d_xB[NN * CC];    // pong
__device__ int   d_tileSum[NTILES];
__device__ int   d_tileOff[NTILES];

// ---------------- preprocessing kernels ----------------
__global__ void k_init() {
    int i = blockIdx.x * blockDim.x + threadIdx.x;
    if (i < NN) {
        d_deg[i] = 0;
        d_rowcnt[i] = 0;
        d_winner[i] = -1;
    }
}

__global__ void k_count(const int* __restrict__ row, const int* __restrict__ col) {
    int e = blockIdx.x * blockDim.x + threadIdx.x;
    if (e < EE) {
        atomicAdd(&d_rowcnt[row[e]], 1);
        atomicAdd(&d_deg[col[e]], 1);
    }
}

__global__ void k_dinv() {
    int i = blockIdx.x * blockDim.x + threadIdx.x;
    if (i < NN) d_dinv[i] = rsqrtf((float)d_deg[i]);  // deg >= 1 guaranteed (self col range)
}

// 3-kernel exclusive scan of d_rowcnt -> d_rowptr (and d_cursor copy)
__global__ void k_scan_reduce() {
    __shared__ int sdata[SCAN_BLOCK];
    int t = threadIdx.x, b = blockIdx.x;
    int base = b * SCAN_TILE;
    int s = 0;
#pragma unroll
    for (int i = 0; i < SCAN_ITEMS; i++) {
        int idx = base + t + i * SCAN_BLOCK;
        if (idx < NN) s += d_rowcnt[idx];
    }
    sdata[t] = s;
    __syncthreads();
    for (int o = SCAN_BLOCK / 2; o > 0; o >>= 1) {
        if (t < o) sdata[t] += sdata[t + o];
        __syncthreads();
    }
    if (t == 0) d_tileSum[b] = sdata[0];
}

__global__ void k_scan_tiles() {
    int acc = 0;
    for (int i = 0; i < NTILES; i++) { d_tileOff[i] = acc; acc += d_tileSum[i]; }
}

__global__ void k_scan_final() {
    __shared__ int ssum[SCAN_BLOCK];
    int t = threadIdx.x, b = blockIdx.x;
    int base = b * SCAN_TILE;
    int v[SCAN_ITEMS];
    int s = 0;
#pragma unroll
    for (int i = 0; i < SCAN_ITEMS; i++) {
        int idx = base + t * SCAN_ITEMS + i;
        v[i] = (idx < NN) ? d_rowcnt[idx] : 0;
        s += v[i];
    }
    ssum[t] = s;
    __syncthreads();
    // Hillis-Steele inclusive scan over thread sums
    for (int o = 1; o < SCAN_BLOCK; o <<= 1) {
        int val = ssum[t];
        int add = (t >= o) ? ssum[t - o] : 0;
        __syncthreads();
        ssum[t] = val + add;
        __syncthreads();
    }
    int run = ((t > 0) ? ssum[t - 1] : 0) + d_tileOff[b];
#pragma unroll
    for (int i = 0; i < SCAN_ITEMS; i++) {
        int idx = base + t * SCAN_ITEMS + i;
        if (idx < NN) {
            d_rowptr[idx] = run;
            d_cursor[idx] = run;
            run += v[i];
        }
    }
}

__global__ void k_fill(const int* __restrict__ row, const int* __restrict__ col) {
    int e = blockIdx.x * blockDim.x + threadIdx.x;
    if (e < EE) {
        int r = row[e], c = col[e];
        float w = d_dinv[r] * d_dinv[c];
        int pos = atomicAdd(&d_cursor[r], 1);
        d_edges[pos] = make_int2(c, __float_as_int(w));
    }
}

__global__ void k_winner(const int* __restrict__ mask) {
    int i = blockIdx.x * blockDim.x + threadIdx.x;
    if (i < MM) atomicMax(&d_winner[mask[i]], i);
}

__global__ void k_buildG(const float* __restrict__ Z, const float* __restrict__ Y) {
    int idx = blockIdx.x * blockDim.x + threadIdx.x;
    if (idx < NN * CC) {
        int n = idx / CC, c = idx % CC;
        int w = d_winner[n];
        d_G[idx] = (w >= 0) ? Y[w * CC + c] : Z[idx];
    }
}

// ---------------- main iteration kernel: warp-per-row CSR SpMM ----------------
// out[r][:] = LAM * sum_e w_e * x[col_e][:] + (1-LAM) * G[r][:]
__global__ void k_spmm(const float* __restrict__ x, float* __restrict__ out) {
    int gw = (blockIdx.x * blockDim.x + threadIdx.x) >> 5;  // global warp = row
    int lane = threadIdx.x & 31;
    if (gw >= NN) return;
    int start = d_rowptr[gw];
    int cnt = d_rowcnt[gw];
    const int2* ep = d_edges + start;
    float a0 = 0.f, a1 = 0.f;
#pragma unroll 4
    for (int i = 0; i < cnt; i++) {
        int2 e = __ldg(&ep[i]);                 // broadcast within warp
        float w = __int_as_float(e.y);
        const float* xr = x + (size_t)e.x * CC;
        a0 = fmaf(w, __ldg(xr + lane), a0);               // cols 0..31
        if (lane < 16) a1 = fmaf(w, __ldg(xr + 32 + lane), a1);  // cols 32..47
    }
    float* o = out + (size_t)gw * CC;
    const float* g = d_G + (size_t)gw * CC;
    o[lane] = LAMF * a0 + (1.f - LAMF) * g[lane];
    if (lane < 16) o[32 + lane] = LAMF * a1 + (1.f - LAMF) * g[32 + lane];
}

// ---------------- launch ----------------
extern "C" void kernel_launch(void* const* d_in, const int* in_sizes, int n_in,
                              void* d_out, int out_size) {
    const float* Z = (const float*)d_in[0];
    const float* Y = (const float*)d_in[1];
    const int* mask = (const int*)d_in[2];
    const int* ei = (const int*)d_in[3];   // [2, E] row-major: row then col
    const int* row = ei;
    const int* col = ei + EE;
    float* out = (float*)d_out;

    float *xA, *xB, *G;
    cudaGetSymbolAddress((void**)&xA, d_xA);
    cudaGetSymbolAddress((void**)&xB, d_xB);
    cudaGetSymbolAddress((void**)&G, d_G);

    const int tb = 256;
    k_init<<<(NN + tb - 1) / tb, tb>>>();
    k_count<<<(EE + tb - 1) / tb, tb>>>(row, col);
    k_dinv<<<(NN + tb - 1) / tb, tb>>>();
    k_scan_reduce<<<NTILES, SCAN_BLOCK>>>();
    k_scan_tiles<<<1, 1>>>();
    k_scan_final<<<NTILES, SCAN_BLOCK>>>();
    k_fill<<<(EE + tb - 1) / tb, tb>>>(row, col);
    k_winner<<<(MM + tb - 1) / tb, tb>>>(mask);
    k_buildG<<<(NN * CC + tb - 1) / tb, tb>>>(Z, Y);

    const float* cur = G;
    for (int it = 0; it < LL; ++it) {
        float* nxt = (it == LL - 1) ? out : ((it & 1) ? xB : xA);
        k_spmm<<<(NN * 32 + tb - 1) / tb, tb>>>(cur, nxt);
        cur = nxt;
    }
}

// round 3
// speedup vs baseline: 1.0080x; 1.0080x over previous
#include <cuda_runtime.h>
#include <cuda_bf16.h>

// Problem constants (fixed by the dataset)
#define NN 100000
#define CC 48
#define EE 1600000
#define MM 20000
#define LL 10
#define LAMF 0.9f
#define OMLAMF 0.1f

#define SCAN_BLOCK 1024
#define SCAN_ITEMS 4
#define SCAN_TILE  (SCAN_BLOCK * SCAN_ITEMS)   // 4096
#define NTILES     ((NN + SCAN_TILE - 1) / SCAN_TILE)  // 25

// padded edge capacity: each row padded to even count -> <= EE + NN entries
#define PADE (EE + NN)            // int2 entries
#define PADE4 ((PADE + 1) / 2)    // int4 entries

// ---------------- device scratch (no allocations allowed) ----------------
__device__ int   d_deg[NN];        // in-degree (by col)
__device__ float d_dinv[NN];       // deg^-0.5
__device__ int   d_rowcnt[NN];     // true out-count per row
__device__ int   d_rowptr[NN];     // CSR row offsets in PADDED space (even)
__device__ int   d_cursor[NN];     // scatter cursors (init = rowptr)
__device__ int   d_winner[NN];     // last mask index targeting node (-1 = none)
__device__ int4  d_edges4[PADE4];  // packed {col0,w0,col1,w1}, grouped by row, pads w=0
__device__ float d_G[NN * CC];     // G = Z with G[mask] = Y (last write wins)
__device__ float d_xA[NN * CC];    // ping
__device__ float d_xB[NN * CC];    // pong
__device__ int   d_tileSum[NTILES];
__device__ int   d_tileOff[NTILES];

__device__ __forceinline__ int padded(int c) { return (c + 1) & ~1; }

// ---------------- preprocessing kernels ----------------
// fused init: node arrays + zero the padded edge array (pads must be w=0)
__global__ void k_init() {
    int i = blockIdx.x * blockDim.x + threadIdx.x;
    if (i < NN) {
        d_deg[i] = 0;
        d_rowcnt[i] = 0;
        d_winner[i] = -1;
    }
    if (i < PADE4) d_edges4[i] = make_int4(0, 0, 0, 0);
}

__global__ void k_count(const int* __restrict__ row, const int* __restrict__ col) {
    int e = blockIdx.x * blockDim.x + threadIdx.x;
    if (e < EE) {
        atomicAdd(&d_rowcnt[row[e]], 1);
        atomicAdd(&d_deg[col[e]], 1);
    }
}

__global__ void k_dinv() {
    int i = blockIdx.x * blockDim.x + threadIdx.x;
    if (i < NN) d_dinv[i] = rsqrtf((float)d_deg[i]);  // deg >= 1 guaranteed
}

// 3-kernel exclusive scan of padded(rowcnt) -> d_rowptr / d_cursor
__global__ void k_scan_reduce() {
    __shared__ int sdata[SCAN_BLOCK];
    int t = threadIdx.x, b = blockIdx.x;
    int base = b * SCAN_TILE;
    int s = 0;
#pragma unroll
    for (int i = 0; i < SCAN_ITEMS; i++) {
        int idx = base + t + i * SCAN_BLOCK;
        if (idx < NN) s += padded(d_rowcnt[idx]);
    }
    sdata[t] = s;
    __syncthreads();
    for (int o = SCAN_BLOCK / 2; o > 0; o >>= 1) {
        if (t < o) sdata[t] += sdata[t + o];
        __syncthreads();
    }
    if (t == 0) d_tileSum[b] = sdata[0];
}

__global__ void k_scan_tiles() {
    int acc = 0;
    for (int i = 0; i < NTILES; i++) { d_tileOff[i] = acc; acc += d_tileSum[i]; }
}

__global__ void k_scan_final() {
    __shared__ int ssum[SCAN_BLOCK];
    int t = threadIdx.x, b = blockIdx.x;
    int base = b * SCAN_TILE;
    int v[SCAN_ITEMS];
    int s = 0;
#pragma unroll
    for (int i = 0; i < SCAN_ITEMS; i++) {
        int idx = base + t * SCAN_ITEMS + i;
        v[i] = (idx < NN) ? padded(d_rowcnt[idx]) : 0;
        s += v[i];
    }
    ssum[t] = s;
    __syncthreads();
    for (int o = 1; o < SCAN_BLOCK; o <<= 1) {
        int val = ssum[t];
        int add = (t >= o) ? ssum[t - o] : 0;
        __syncthreads();
        ssum[t] = val + add;
        __syncthreads();
    }
    int run = ((t > 0) ? ssum[t - 1] : 0) + d_tileOff[b];
#pragma unroll
    for (int i = 0; i < SCAN_ITEMS; i++) {
        int idx = base + t * SCAN_ITEMS + i;
        if (idx < NN) {
            d_rowptr[idx] = run;
            d_cursor[idx] = run;
            run += v[i];
        }
    }
}

__global__ void k_fill(const int* __restrict__ row, const int* __restrict__ col) {
    int e = blockIdx.x * blockDim.x + threadIdx.x;
    if (e < EE) {
        int r = row[e], c = col[e];
        float w = d_dinv[r] * d_dinv[c];
        int pos = atomicAdd(&d_cursor[r], 1);
        ((int2*)d_edges4)[pos] = make_int2(c, __float_as_int(w));
    }
}

__global__ void k_winner(const int* __restrict__ mask) {
    int i = blockIdx.x * blockDim.x + threadIdx.x;
    if (i < MM) atomicMax(&d_winner[mask[i]], i);
}

__global__ void k_buildG(const float* __restrict__ Z, const float* __restrict__ Y) {
    int idx = blockIdx.x * blockDim.x + threadIdx.x;
    if (idx < NN * CC) {
        int n = idx / CC, c = idx % CC;
        int w = d_winner[n];
        d_G[idx] = (w >= 0) ? Y[w * CC + c] : Z[idx];
    }
}

// ---------------- main iteration kernel: warp-per-row CSR SpMM ----------------
// Layout: 1 warp = 1 row. Each loop trip consumes TWO edges:
//   half-warp 0 (lanes 0-15, active lanes sub<12) gathers edge[2i]   as float4
//   half-warp 1 (lanes 16-31, active lanes sub<12) gathers edge[2i+1] as float4
// Both halves share one broadcast int4 edge-pair load. Pads have w=0.
// Final shfl_xor(16) merges the two half accumulators.
__global__ void k_spmm(const float* __restrict__ x, float* __restrict__ out) {
    int gw = (blockIdx.x * blockDim.x + threadIdx.x) >> 5;  // global warp = row
    if (gw >= NN) return;
    int lane = threadIdx.x & 31;
    int half = lane >> 4;
    int sub = lane & 15;
    bool active = sub < 12;

    int start = d_rowptr[gw];                 // even, in int2 units
    int npair = (d_rowcnt[gw] + 1) >> 1;      // padded pair count
    const int4* ep = d_edges4 + (start >> 1);

    float4 acc = make_float4(0.f, 0.f, 0.f, 0.f);
    int fofs = sub * 4;
#pragma unroll 2
    for (int i = 0; i < npair; i++) {
        int4 e2 = __ldg(&ep[i]);              // {col0, w0bits, col1, w1bits}
        int c = half ? e2.z : e2.x;
        float w = __int_as_float(half ? e2.w : e2.y);
        if (active) {
            const float4 v = *(const float4*)(x + (size_t)c * CC + fofs);
            acc.x = fmaf(w, v.x, acc.x);
            acc.y = fmaf(w, v.y, acc.y);
            acc.z = fmaf(w, v.z, acc.z);
            acc.w = fmaf(w, v.w, acc.w);
        }
    }
    // merge half-warps
    acc.x += __shfl_xor_sync(0xffffffff, acc.x, 16);
    acc.y += __shfl_xor_sync(0xffffffff, acc.y, 16);
    acc.z += __shfl_xor_sync(0xffffffff, acc.z, 16);
    acc.w += __shfl_xor_sync(0xffffffff, acc.w, 16);

    if (half == 0 && active) {
        const float4 g = *(const float4*)(d_G + (size_t)gw * CC + fofs);
        float4 o;
        o.x = fmaf(LAMF, acc.x, OMLAMF * g.x);
        o.y = fmaf(LAMF, acc.y, OMLAMF * g.y);
        o.z = fmaf(LAMF, acc.z, OMLAMF * g.z);
        o.w = fmaf(LAMF, acc.w, OMLAMF * g.w);
        *(float4*)(out + (size_t)gw * CC + fofs) = o;
    }
}

// ---------------- launch ----------------
extern "C" void kernel_launch(void* const* d_in, const int* in_sizes, int n_in,
                              void* d_out, int out_size) {
    const float* Z = (const float*)d_in[0];
    const float* Y = (const float*)d_in[1];
    const int* mask = (const int*)d_in[2];
    const int* ei = (const int*)d_in[3];   // [2, E] row-major: row then col
    const int* row = ei;
    const int* col = ei + EE;
    float* out = (float*)d_out;

    float *xA, *xB, *G;
    cudaGetSymbolAddress((void**)&xA, d_xA);
    cudaGetSymbolAddress((void**)&xB, d_xB);
    cudaGetSymbolAddress((void**)&G, d_G);

    const int tb = 256;
    int initN = (PADE4 > NN) ? PADE4 : NN;
    k_init<<<(initN + tb - 1) / tb, tb>>>();
    k_count<<<(EE + tb - 1) / tb, tb>>>(row, col);
    k_dinv<<<(NN + tb - 1) / tb, tb>>>();
    k_scan_reduce<<<NTILES, SCAN_BLOCK>>>();
    k_scan_tiles<<<1, 1>>>();
    k_scan_final<<<NTILES, SCAN_BLOCK>>>();
    k_fill<<<(EE + tb - 1) / tb, tb>>>(row, col);
    k_winner<<<(MM + tb - 1) / tb, tb>>>(mask);
    k_buildG<<<(NN * CC + tb - 1) / tb, tb>>>(Z, Y);

    const float* cur = G;
    for (int it = 0; it < LL; ++it) {
        float* nxt = (it == LL - 1) ? out : ((it & 1) ? xB : xA);
        k_spmm<<<(NN * 32 + tb - 1) / tb, tb>>>(cur, nxt);
        cur = nxt;
    }
}

// round 4
// speedup vs baseline: 1.1299x; 1.1209x over previous
#include <cuda_runtime.h>
#include <cuda_fp16.h>

// Problem constants (fixed by the dataset)
#define NN 100000
#define CC 48
#define EE 1600000
#define MM 20000
#define LL 10
#define LAMF 0.9f
#define OMLAMF 0.1f

#define SCAN_BLOCK 1024
#define SCAN_ITEMS 4
#define SCAN_TILE  (SCAN_BLOCK * SCAN_ITEMS)            // 4096
#define NTILES     ((NN + SCAN_TILE - 1) / SCAN_TILE)   // 25

// padded edge capacity: each row padded to even count -> <= EE + NN int2 entries
#define PADE  (EE + NN)
#define PADE4 ((PADE + 1) / 2)

// ---------------- device scratch (no allocations allowed) ----------------
__device__ int    d_deg[NN];
__device__ float  d_dinv[NN];
__device__ int    d_rowcnt[NN];       // true out-count per row
__device__ int    d_rowptr[NN];       // CSR offsets in PADDED (even) int2 space
__device__ int    d_cursor[NN];
__device__ int    d_winner[NN];       // last mask index targeting node (-1 = none)
__device__ int4   d_edges4[PADE4];    // {col0,w0,col1,w1} pairs per row; pads w=0
__device__ float  d_G[NN * CC];       // fp32 anchor
__device__ __half d_xA[NN * CC];      // fp16 ping
__device__ __half d_xB[NN * CC];      // fp16 pong (also holds x0 = fp16(G))
__device__ int    d_tileSum[NTILES];

__device__ __forceinline__ int padded(int c) { return (c + 1) & ~1; }

// ---------------- preprocessing (exactly 5 kernels) ----------------
__global__ void k_init() {
    int i = blockIdx.x * blockDim.x + threadIdx.x;
    if (i < NN) {
        d_deg[i] = 0;
        d_rowcnt[i] = 0;
        d_winner[i] = -1;
    }
}

// edge counting + masked-label winner selection fused
__global__ void k_count(const int* __restrict__ row, const int* __restrict__ col,
                        const int* __restrict__ mask) {
    int e = blockIdx.x * blockDim.x + threadIdx.x;
    if (e < EE) {
        atomicAdd(&d_rowcnt[row[e]], 1);
        atomicAdd(&d_deg[col[e]], 1);
    }
    if (e < MM) atomicMax(&d_winner[mask[e]], e);
}

// per-tile sums of padded counts + dinv computation fused
__global__ void k_scan_reduce() {
    __shared__ int sdata[SCAN_BLOCK];
    int t = threadIdx.x, b = blockIdx.x;
    int base = b * SCAN_TILE;
    int s = 0;
#pragma unroll
    for (int i = 0; i < SCAN_ITEMS; i++) {
        int idx = base + t + i * SCAN_BLOCK;
        if (idx < NN) {
            s += padded(d_rowcnt[idx]);
            d_dinv[idx] = rsqrtf((float)d_deg[idx]);   // deg >= 1 guaranteed
        }
    }
    sdata[t] = s;
    __syncthreads();
    for (int o = SCAN_BLOCK / 2; o > 0; o >>= 1) {
        if (t < o) sdata[t] += sdata[t + o];
        __syncthreads();
    }
    if (t == 0) d_tileSum[b] = sdata[0];
}

// final scan: every block redundantly scans the 25 tile sums, then writes
// rowptr/cursor, and directly writes the w=0 pad slot for odd-count rows
// (replaces zeroing the whole 12.8MB edge array).
__global__ void k_scan_final() {
    __shared__ int ssum[SCAN_BLOCK];
    int t = threadIdx.x, b = blockIdx.x;
    int base = b * SCAN_TILE;
    int tileOff = 0;
    for (int i = 0; i < b; i++) tileOff += d_tileSum[i];   // NTILES=25, trivial

    int tc[SCAN_ITEMS], v[SCAN_ITEMS];
    int s = 0;
#pragma unroll
    for (int i = 0; i < SCAN_ITEMS; i++) {
        int idx = base + t * SCAN_ITEMS + i;
        tc[i] = (idx < NN) ? d_rowcnt[idx] : 0;
        v[i] = padded(tc[i]) & ~(idx >= NN);   // 0 beyond NN (tc=0 -> padded=0 anyway)
        v[i] = (idx < NN) ? padded(tc[i]) : 0;
        s += v[i];
    }
    ssum[t] = s;
    __syncthreads();
    for (int o = 1; o < SCAN_BLOCK; o <<= 1) {
        int val = ssum[t];
        int add = (t >= o) ? ssum[t - o] : 0;
        __syncthreads();
        ssum[t] = val + add;
        __syncthreads();
    }
    int run = ((t > 0) ? ssum[t - 1] : 0) + tileOff;
#pragma unroll
    for (int i = 0; i < SCAN_ITEMS; i++) {
        int idx = base + t * SCAN_ITEMS + i;
        if (idx < NN) {
            d_rowptr[idx] = run;
            d_cursor[idx] = run;
            if (tc[i] & 1)   // odd count -> write the pad slot (col=0, w=0)
                ((int2*)d_edges4)[run + tc[i]] = make_int2(0, 0);
            run += v[i];
        }
    }
}

// edge fill (counting-sort scatter) + G build + fp16 x0 write, fused
__global__ void k_fill_buildG(const int* __restrict__ row, const int* __restrict__ col,
                              const float* __restrict__ Z, const float* __restrict__ Y) {
    int idx = blockIdx.x * blockDim.x + threadIdx.x;
    if (idx < EE) {
        int r = row[idx], c = col[idx];
        float w = d_dinv[r] * d_dinv[c];
        int pos = atomicAdd(&d_cursor[r], 1);
        ((int2*)d_edges4)[pos] = make_int2(c, __float_as_int(w));
    }
    if (idx < NN * CC) {
        int n = idx / CC, c = idx % CC;
        int wi = d_winner[n];
        float g = (wi >= 0) ? Y[wi * CC + c] : Z[idx];
        d_G[idx] = g;
        d_xB[idx] = __float2half_rn(g);   // x0 lives in the pong buffer
    }
}

// ---------------- main iteration: warp-per-row CSR SpMM, fp16 gather ----------------
// 1 warp = 1 row; each trip consumes 2 edges via one broadcast int4.
// half-warp h handles edge 2i+h; 12 active lanes each gather 4 halves (8B ldg).
// fp32 accumulate; shfl_xor(16) merges halves. FINAL=true writes fp32 d_out.
template <bool FINAL>
__global__ void k_spmm(const __half* __restrict__ x, void* __restrict__ outp) {
    int gw = (blockIdx.x * blockDim.x + threadIdx.x) >> 5;
    if (gw >= NN) return;
    int lane = threadIdx.x & 31;
    int half = lane >> 4;
    int sub = lane & 15;
    bool active = sub < 12;

    int start = d_rowptr[gw];                 // even (int2 units)
    int npair = (d_rowcnt[gw] + 1) >> 1;
    const int4* ep = d_edges4 + (start >> 1);

    float4 acc = make_float4(0.f, 0.f, 0.f, 0.f);
    int hofs = sub * 4;                       // half-element offset within row
#pragma unroll 2
    for (int i = 0; i < npair; i++) {
        int4 e2 = __ldg(&ep[i]);
        int c = half ? e2.z : e2.x;
        float w = __int_as_float(half ? e2.w : e2.y);
        if (active) {
            uint2 raw = __ldg(reinterpret_cast<const uint2*>(x + (size_t)c * CC + hofs));
            __half2 h0, h1;
            *reinterpret_cast<unsigned*>(&h0) = raw.x;
            *reinterpret_cast<unsigned*>(&h1) = raw.y;
            float2 f0 = __half22float2(h0);
            float2 f1 = __half22float2(h1);
            acc.x = fmaf(w, f0.x, acc.x);
            acc.y = fmaf(w, f0.y, acc.y);
            acc.z = fmaf(w, f1.x, acc.z);
            acc.w = fmaf(w, f1.y, acc.w);
        }
    }
    acc.x += __shfl_xor_sync(0xffffffff, acc.x, 16);
    acc.y += __shfl_xor_sync(0xffffffff, acc.y, 16);
    acc.z += __shfl_xor_sync(0xffffffff, acc.z, 16);
    acc.w += __shfl_xor_sync(0xffffffff, acc.w, 16);

    if (half == 0 && active) {
        const float4 g = *(const float4*)(d_G + (size_t)gw * CC + hofs);
        float4 o;
        o.x = fmaf(LAMF, acc.x, OMLAMF * g.x);
        o.y = fmaf(LAMF, acc.y, OMLAMF * g.y);
        o.z = fmaf(LAMF, acc.z, OMLAMF * g.z);
        o.w = fmaf(LAMF, acc.w, OMLAMF * g.w);
        if (FINAL) {
            *(float4*)((float*)outp + (size_t)gw * CC + hofs) = o;
        } else {
            __half2 o0 = __floats2half2_rn(o.x, o.y);
            __half2 o1 = __floats2half2_rn(o.z, o.w);
            uint2 st;
            st.x = *reinterpret_cast<unsigned*>(&o0);
            st.y = *reinterpret_cast<unsigned*>(&o1);
            *(uint2*)((__half*)outp + (size_t)gw * CC + hofs) = st;
        }
    }
}

// ---------------- launch ----------------
extern "C" void kernel_launch(void* const* d_in, const int* in_sizes, int n_in,
                              void* d_out, int out_size) {
    const float* Z = (const float*)d_in[0];
    const float* Y = (const float*)d_in[1];
    const int* mask = (const int*)d_in[2];
    const int* ei = (const int*)d_in[3];   // [2, E]: row then col
    const int* row = ei;
    const int* col = ei + EE;

    __half *xA, *xB;
    cudaGetSymbolAddress((void**)&xA, d_xA);
    cudaGetSymbolAddress((void**)&xB, d_xB);

    const int tb = 256;
    k_init<<<(NN + tb - 1) / tb, tb>>>();
    k_count<<<(EE + tb - 1) / tb, tb>>>(row, col, mask);
    k_scan_reduce<<<NTILES, SCAN_BLOCK>>>();
    k_scan_final<<<NTILES, SCAN_BLOCK>>>();
    k_fill_buildG<<<(NN * CC + tb - 1) / tb, tb>>>(row, col, Z, Y);

    const int spmm_blocks = (NN * 32 + tb - 1) / tb;
    const __half* cur = xB;                   // x0 = fp16(G) lives in xB
    for (int it = 0; it < LL - 1; ++it) {
        __half* nxt = (it & 1) ? xB : xA;
        k_spmm<false><<<spmm_blocks, tb>>>(cur, nxt);
        cur = nxt;
    }
    k_spmm<true><<<spmm_blocks, tb>>>(cur, d_out);
}